// round 12
// baseline (speedup 1.0000x reference)
#include <cuda_runtime.h>
#include <cuda_bf16.h>
#include <math.h>

// ---------------------------------------------------------------------------
// CGCA branch, fully collapsed, single kernel (+ tiny counter memset):
//   gc = adj·fc1·blockdiag(w2)·w1·avg = B·avg  (linear chain up to relu).
// Blocks 0..16      : build row j of B[17,512]; publish via red.release.
// Blocks 17..17+4095: pool 8 (n,c) rows each; the last-finishing block of
//                     each batch (acq_rel ticket) computes
//                     out[b,:] = sigmoid(fc2·relu(B·avg_b)).
// Sync cost: ONE scoped atomic per block (t0), no per-thread fences.
// ---------------------------------------------------------------------------

#define J    17
#define C    512
#define CA   272
#define HW   3136          // 56*56
#define HW4  784           // HW/4
#define NEG  (-9e15f)
#define JJ   289           // J*J

// flatnonzero(ADJ) — 49 entries
__constant__ int NZ[49] = {
      0,   1,
     17,  18,  19,
     35,  36,  40,
     54,  55,  57,
     71,  72,  73,
     89,  90,
    104, 105, 108, 109,
    125, 126, 127,
    143, 144, 147, 148, 152,
    162, 169,
    180, 181,
    197, 198, 199,
    212, 215, 216,
    229, 234, 235,
    251, 252, 253,
    269, 270,
    280, 281, 288
};

// scratch (static device globals — no allocation)
__device__ float g_avg[256 * C];     // pooled features, max batch 256
__device__ float g_B[J * C];         // collapsed linear map [17, 512]
__device__ int   g_sync[260];        // [0] = B-ready count; [4+b] = batch tickets

// ---- scoped atomic helpers (t0-only; cumulativity publishes block writes) --
__device__ __forceinline__ int atom_add_acq_rel_gpu(int* p, int v) {
    int old;
    asm volatile("atom.acq_rel.gpu.global.add.s32 %0, [%1], %2;"
                 : "=r"(old) : "l"(p), "r"(v) : "memory");
    return old;
}
__device__ __forceinline__ void red_add_release_gpu(int* p, int v) {
    asm volatile("red.release.gpu.global.add.s32 [%0], %1;"
                 :: "l"(p), "r"(v) : "memory");
}
__device__ __forceinline__ int ld_acquire_gpu(const int* p) {
    int v;
    asm volatile("ld.acquire.gpu.global.s32 %0, [%1];"
                 : "=r"(v) : "l"(p) : "memory");
    return v;
}

__global__ __launch_bounds__(256, 6) void fused_kernel(
    const float* __restrict__ x,     // [n*C*HW]
    const float* __restrict__ e,     // [49]
    const float* __restrict__ fc1,   // [J, CA]
    const float* __restrict__ w2,    // [CA, J]  (blockdiag groups [16,J,J])
    const float* __restrict__ w1,    // [CA, C]
    const float* __restrict__ fc2,   // [C, J]
    float* __restrict__ out,         // [n, C]
    int rows)
{
    __shared__ float adjs[JJ];
    __shared__ float arow[J];
    __shared__ float F[CA];
    __shared__ float T[CA];
    __shared__ float avgs[C];
    __shared__ float gcs[J];
    __shared__ int   ticket_s;

    const int t = threadIdx.x;

    if (blockIdx.x < J) {
        // ================= precompute branch: row j of B =================
        const int j = blockIdx.x;

        for (int idx = t; idx < JJ; idx += 256) adjs[idx] = NEG;  // all 289
        __syncthreads();
        if (t < 49) adjs[NZ[t]] = e[t];
        __syncthreads();

        if (t == 0) {
            float m = NEG;
#pragma unroll
            for (int k = 0; k < J; k++) m = fmaxf(m, adjs[j * J + k]);
            float s = 0.f, tmp[J];
#pragma unroll
            for (int k = 0; k < J; k++) { tmp[k] = expf(adjs[j * J + k] - m); s += tmp[k]; }
            float inv = 1.0f / s;
#pragma unroll
            for (int k = 0; k < J; k++) arow[k] = tmp[k] * inv;
        }
        __syncthreads();

        // F[k] = sum_{j2} arow[j2] * fc1[j2, k]
        for (int idx = t; idx < CA; idx += 256) {
            float s = 0.f;
#pragma unroll
            for (int j2 = 0; j2 < J; j2++) s += arow[j2] * fc1[j2 * CA + idx];
            F[idx] = s;
        }
        __syncthreads();

        // T[g*17+i] = sum_o F[g*17+o] * w2[(g*17+o)*17 + i]
        for (int idx = t; idx < CA; idx += 256) {
            int g = idx / J, i = idx % J;
            float s = 0.f;
#pragma unroll
            for (int o = 0; o < J; o++) s += F[g * J + o] * w2[(g * J + o) * J + i];
            T[idx] = s;
        }
        __syncthreads();

        // B[j, c] = sum_k T[k] * w1[k, c] ; thread covers c = t and t+256.
        {
            float a0 = 0.f, a1 = 0.f, a2 = 0.f, a3 = 0.f;
            float b0 = 0.f, b1 = 0.f, b2 = 0.f, b3 = 0.f;
#pragma unroll
            for (int k = 0; k < CA / 4; k++) {
                const float* r0 = w1 + (4 * k + 0) * C;
                const float* r1 = w1 + (4 * k + 1) * C;
                const float* r2 = w1 + (4 * k + 2) * C;
                const float* r3 = w1 + (4 * k + 3) * C;
                a0 += T[4 * k + 0] * r0[t];
                a1 += T[4 * k + 1] * r1[t];
                a2 += T[4 * k + 2] * r2[t];
                a3 += T[4 * k + 3] * r3[t];
                b0 += T[4 * k + 0] * r0[t + 256];
                b1 += T[4 * k + 1] * r1[t + 256];
                b2 += T[4 * k + 2] * r2[t + 256];
                b3 += T[4 * k + 3] * r3[t + 256];
            }
            g_B[j * C + t]       = (a0 + a1) + (a2 + a3);
            g_B[j * C + t + 256] = (b0 + b1) + (b2 + b3);
        }

        // publish B row: syncthreads orders block writes for t0; release
        // promotes them to gpu scope (cumulativity).
        __syncthreads();
        if (t == 0) red_add_release_gpu(&g_sync[0], 1);
        return;
    }

    // ================= pool branch: 8 warps, one (n,c) row each ==========
    {
        const int rb   = blockIdx.x - J;            // row-block 0..4095
        const int warp = rb * 8 + (t >> 5);
        const int lane = t & 31;
        const int b    = rb >> 6;                   // 64 row-blocks per batch

        if (warp < rows) {
            const float4* p = reinterpret_cast<const float4*>(x) + (size_t)warp * HW4;

            float4 a = make_float4(0.f, 0.f, 0.f, 0.f);
#pragma unroll
            for (int i = 0; i < 24; i++) {
                float4 v = __ldcs(&p[lane + i * 32]);
                a.x += v.x; a.y += v.y; a.z += v.z; a.w += v.w;
            }
            if (lane < 16) {               // 784 - 24*32 = 16 tail vec4s
                float4 v = __ldcs(&p[768 + lane]);
                a.x += v.x; a.y += v.y; a.z += v.z; a.w += v.w;
            }
            float s = (a.x + a.y) + (a.z + a.w);
#pragma unroll
            for (int o = 16; o; o >>= 1) s += __shfl_xor_sync(0xffffffffu, s, o);

            if (lane == 0) g_avg[warp] = s * (1.0f / (float)HW);
        }

        // one acq_rel atomic per block: releases this block's g_avg writes,
        // acquires the other 63 blocks' writes for the winner.
        __syncthreads();
        if (t == 0) ticket_s = atom_add_acq_rel_gpu(&g_sync[4 + b], 1);
        __syncthreads();
        if (ticket_s != 63) return;        // not the last block of this batch

        // ---- last block of batch b: finish the channel attention ----
        if (t == 0) {                      // wait for all 17 B rows
            while (ld_acquire_gpu(&g_sync[0]) < J) { }
        }
        __syncthreads();

        avgs[t]       = g_avg[b * C + t];
        avgs[t + 256] = g_avg[b * C + t + 256];
        __syncthreads();

        // gc[j] = relu(dot(B[j,:], avg)) — 8 warps cover 17 rows
        {
            const int wid = t >> 5;
            for (int j = wid; j < J; j += 8) {
                const float* wr = g_B + (size_t)j * C;
                float s = 0.f;
#pragma unroll
                for (int k = lane; k < C; k += 32) s += avgs[k] * wr[k];
#pragma unroll
                for (int off = 16; off; off >>= 1)
                    s += __shfl_xor_sync(0xffffffffu, s, off);
                if (lane == 0) gcs[j] = fmaxf(s, 0.f);
            }
        }
        __syncthreads();

        // out[b, c] = sigmoid(dot(gc, fc2[c,:])) — c = t and t+256
#pragma unroll
        for (int h = 0; h < 2; h++) {
            int c = t + h * 256;
            const float* wr = fc2 + (size_t)c * J;
            float s = 0.f;
#pragma unroll
            for (int j = 0; j < J; j++) s += gcs[j] * wr[j];
            out[b * C + c] = 1.0f / (1.0f + expf(-s));
        }
    }
}

// ---------------------------------------------------------------------------
extern "C" void kernel_launch(void* const* d_in, const int* in_sizes, int n_in,
                              void* d_out, int out_size)
{
    const float* x    = (const float*)d_in[0];
    const float* e    = (const float*)d_in[1];
    const float* w1   = (const float*)d_in[2];
    const float* w2   = (const float*)d_in[3];
    const float* fc1w = (const float*)d_in[4];
    const float* fc2w = (const float*)d_in[5];
    float* out = (float*)d_out;

    int n    = in_sizes[0] / (C * HW);   // 64
    int rows = n * C;                    // 32768

    void* syncp;
    cudaGetSymbolAddress(&syncp, g_sync);
    cudaMemsetAsync(syncp, 0, sizeof(int) * (4 + n));   // replay-safe reset

    int grid = J + (rows + 7) / 8;       // 17 precompute + 4096 pool blocks
    fused_kernel<<<grid, 256>>>(x, e, fc1w, w2, w1, fc2w, out, rows);
}

// round 13
// speedup vs baseline: 1.0322x; 1.0322x over previous
#include <cuda_runtime.h>
#include <cuda_bf16.h>
#include <math.h>

// ---------------------------------------------------------------------------
// CGCA branch, fully collapsed, single kernel (+ tiny counter memset):
//   gc = adj·fc1·blockdiag(w2)·w1·avg = B·avg  (linear chain up to relu).
// Blocks 0..16      : build row j of B[17,512]; publish via red.release.
// Blocks 17..17+4095: pool 8 (n,c) rows each; the last-finishing block of
//                     each batch (acq_rel ticket) computes
//                     out[b,:] = sigmoid(fc2·relu(B·avg_b)).
// Sync: ONE t0-scoped atomic per block (cumulativity publishes block writes).
// launch_bounds(256,4): regs=64 so ptxas front-batches float4 loads (high
// per-warp MLP) — R12 showed regs=40 costs ~7% of HBM bandwidth.
// ---------------------------------------------------------------------------

#define J    17
#define C    512
#define CA   272
#define HW   3136          // 56*56
#define HW4  784           // HW/4
#define NEG  (-9e15f)
#define JJ   289           // J*J

// flatnonzero(ADJ) — 49 entries
__constant__ int NZ[49] = {
      0,   1,
     17,  18,  19,
     35,  36,  40,
     54,  55,  57,
     71,  72,  73,
     89,  90,
    104, 105, 108, 109,
    125, 126, 127,
    143, 144, 147, 148, 152,
    162, 169,
    180, 181,
    197, 198, 199,
    212, 215, 216,
    229, 234, 235,
    251, 252, 253,
    269, 270,
    280, 281, 288
};

// scratch (static device globals — no allocation)
__device__ float g_avg[256 * C];     // pooled features, max batch 256
__device__ float g_B[J * C];         // collapsed linear map [17, 512]
__device__ int   g_sync[260];        // [0] = B-ready count; [4+b] = batch tickets

// ---- scoped atomic helpers (t0-only; cumulativity publishes block writes) --
__device__ __forceinline__ int atom_add_acq_rel_gpu(int* p, int v) {
    int old;
    asm volatile("atom.acq_rel.gpu.global.add.s32 %0, [%1], %2;"
                 : "=r"(old) : "l"(p), "r"(v) : "memory");
    return old;
}
__device__ __forceinline__ void red_add_release_gpu(int* p, int v) {
    asm volatile("red.release.gpu.global.add.s32 [%0], %1;"
                 :: "l"(p), "r"(v) : "memory");
}
__device__ __forceinline__ int ld_acquire_gpu(const int* p) {
    int v;
    asm volatile("ld.acquire.gpu.global.s32 %0, [%1];"
                 : "=r"(v) : "l"(p) : "memory");
    return v;
}

__global__ __launch_bounds__(256, 4) void fused_kernel(
    const float* __restrict__ x,     // [n*C*HW]
    const float* __restrict__ e,     // [49]
    const float* __restrict__ fc1,   // [J, CA]
    const float* __restrict__ w2,    // [CA, J]  (blockdiag groups [16,J,J])
    const float* __restrict__ w1,    // [CA, C]
    const float* __restrict__ fc2,   // [C, J]
    float* __restrict__ out,         // [n, C]
    int rows)
{
    __shared__ float adjs[JJ];
    __shared__ float arow[J];
    __shared__ float F[CA];
    __shared__ float T[CA];
    __shared__ float avgs[C];
    __shared__ float gcs[J];
    __shared__ int   ticket_s;

    const int t = threadIdx.x;

    if (blockIdx.x < J) {
        // ================= precompute branch: row j of B =================
        const int j = blockIdx.x;

        for (int idx = t; idx < JJ; idx += 256) adjs[idx] = NEG;  // all 289
        __syncthreads();
        if (t < 49) adjs[NZ[t]] = e[t];
        __syncthreads();

        if (t == 0) {
            float m = NEG;
#pragma unroll
            for (int k = 0; k < J; k++) m = fmaxf(m, adjs[j * J + k]);
            float s = 0.f, tmp[J];
#pragma unroll
            for (int k = 0; k < J; k++) { tmp[k] = expf(adjs[j * J + k] - m); s += tmp[k]; }
            float inv = 1.0f / s;
#pragma unroll
            for (int k = 0; k < J; k++) arow[k] = tmp[k] * inv;
        }
        __syncthreads();

        // F[k] = sum_{j2} arow[j2] * fc1[j2, k]
        for (int idx = t; idx < CA; idx += 256) {
            float s = 0.f;
#pragma unroll
            for (int j2 = 0; j2 < J; j2++) s += arow[j2] * fc1[j2 * CA + idx];
            F[idx] = s;
        }
        __syncthreads();

        // T[g*17+i] = sum_o F[g*17+o] * w2[(g*17+o)*17 + i]
        for (int idx = t; idx < CA; idx += 256) {
            int g = idx / J, i = idx % J;
            float s = 0.f;
#pragma unroll
            for (int o = 0; o < J; o++) s += F[g * J + o] * w2[(g * J + o) * J + i];
            T[idx] = s;
        }
        __syncthreads();

        // B[j, c] = sum_k T[k] * w1[k, c] ; thread covers c = t and t+256.
        {
            float a0 = 0.f, a1 = 0.f, a2 = 0.f, a3 = 0.f;
            float b0 = 0.f, b1 = 0.f, b2 = 0.f, b3 = 0.f;
#pragma unroll
            for (int k = 0; k < CA / 4; k++) {
                const float* r0 = w1 + (4 * k + 0) * C;
                const float* r1 = w1 + (4 * k + 1) * C;
                const float* r2 = w1 + (4 * k + 2) * C;
                const float* r3 = w1 + (4 * k + 3) * C;
                a0 += T[4 * k + 0] * r0[t];
                a1 += T[4 * k + 1] * r1[t];
                a2 += T[4 * k + 2] * r2[t];
                a3 += T[4 * k + 3] * r3[t];
                b0 += T[4 * k + 0] * r0[t + 256];
                b1 += T[4 * k + 1] * r1[t + 256];
                b2 += T[4 * k + 2] * r2[t + 256];
                b3 += T[4 * k + 3] * r3[t + 256];
            }
            g_B[j * C + t]       = (a0 + a1) + (a2 + a3);
            g_B[j * C + t + 256] = (b0 + b1) + (b2 + b3);
        }

        // publish B row: syncthreads orders block writes for t0; release
        // promotes them to gpu scope (cumulativity).
        __syncthreads();
        if (t == 0) red_add_release_gpu(&g_sync[0], 1);
        return;
    }

    // ================= pool branch: 8 warps, one (n,c) row each ==========
    {
        const int rb   = blockIdx.x - J;            // row-block 0..4095
        const int warp = rb * 8 + (t >> 5);
        const int lane = t & 31;
        const int b    = rb >> 6;                   // 64 row-blocks per batch

        if (warp < rows) {
            const float4* p = reinterpret_cast<const float4*>(x) + (size_t)warp * HW4;

            float4 a = make_float4(0.f, 0.f, 0.f, 0.f);
#pragma unroll
            for (int i = 0; i < 24; i++) {
                float4 v = __ldcs(&p[lane + i * 32]);
                a.x += v.x; a.y += v.y; a.z += v.z; a.w += v.w;
            }
            if (lane < 16) {               // 784 - 24*32 = 16 tail vec4s
                float4 v = __ldcs(&p[768 + lane]);
                a.x += v.x; a.y += v.y; a.z += v.z; a.w += v.w;
            }
            float s = (a.x + a.y) + (a.z + a.w);
#pragma unroll
            for (int o = 16; o; o >>= 1) s += __shfl_xor_sync(0xffffffffu, s, o);

            if (lane == 0) g_avg[warp] = s * (1.0f / (float)HW);
        }

        // one acq_rel atomic per block: releases this block's g_avg writes,
        // acquires the other 63 blocks' writes for the winner.
        __syncthreads();
        if (t == 0) ticket_s = atom_add_acq_rel_gpu(&g_sync[4 + b], 1);
        __syncthreads();
        if (ticket_s != 63) return;        // not the last block of this batch

        // ---- last block of batch b: finish the channel attention ----
        if (t == 0) {                      // wait for all 17 B rows
            while (ld_acquire_gpu(&g_sync[0]) < J) { }
        }
        __syncthreads();

        avgs[t]       = g_avg[b * C + t];
        avgs[t + 256] = g_avg[b * C + t + 256];
        __syncthreads();

        // gc[j] = relu(dot(B[j,:], avg)) — 8 warps cover 17 rows
        {
            const int wid = t >> 5;
            for (int j = wid; j < J; j += 8) {
                const float* wr = g_B + (size_t)j * C;
                float s = 0.f;
#pragma unroll
                for (int k = lane; k < C; k += 32) s += avgs[k] * wr[k];
#pragma unroll
                for (int off = 16; off; off >>= 1)
                    s += __shfl_xor_sync(0xffffffffu, s, off);
                if (lane == 0) gcs[j] = fmaxf(s, 0.f);
            }
        }
        __syncthreads();

        // out[b, c] = sigmoid(dot(gc, fc2[c,:])) — c = t and t+256
#pragma unroll
        for (int h = 0; h < 2; h++) {
            int c = t + h * 256;
            const float* wr = fc2 + (size_t)c * J;
            float s = 0.f;
#pragma unroll
            for (int j = 0; j < J; j++) s += gcs[j] * wr[j];
            out[b * C + c] = 1.0f / (1.0f + expf(-s));
        }
    }
}

// ---------------------------------------------------------------------------
extern "C" void kernel_launch(void* const* d_in, const int* in_sizes, int n_in,
                              void* d_out, int out_size)
{
    const float* x    = (const float*)d_in[0];
    const float* e    = (const float*)d_in[1];
    const float* w1   = (const float*)d_in[2];
    const float* w2   = (const float*)d_in[3];
    const float* fc1w = (const float*)d_in[4];
    const float* fc2w = (const float*)d_in[5];
    float* out = (float*)d_out;

    int n    = in_sizes[0] / (C * HW);   // 64
    int rows = n * C;                    // 32768

    void* syncp;
    cudaGetSymbolAddress(&syncp, g_sync);
    cudaMemsetAsync(syncp, 0, sizeof(int) * (4 + n));   // replay-safe reset

    int grid = J + (rows + 7) / 8;       // 17 precompute + 4096 pool blocks
    fused_kernel<<<grid, 256>>>(x, e, fc1w, w2, w1, fc2w, out, rows);
}

// round 15
// speedup vs baseline: 1.0634x; 1.0302x over previous
#include <cuda_runtime.h>
#include <cuda_bf16.h>
#include <math.h>

// ---------------------------------------------------------------------------
// CGCA branch, fully collapsed:
//   gc = adj·fc1·blockdiag(w2)·w1·avg = B·avg   (linear chain up to relu).
// Kernel 1 (fused): blocks 0..16 build B[17,512]; blocks 17.. pool 8 (n,c)
//   rows each. No inter-block sync — blocks exit when their writes are done.
//   (R13 showed in-kernel tail+tickets cost ~6us of pool bandwidth, more
//    than the separate final kernel they replace.)
// Kernel 2: per-batch: gc = relu(B·avg), out = sigmoid(fc2·gc).
// ---------------------------------------------------------------------------

#define J    17
#define C    512
#define CA   272
#define HW   3136          // 56*56
#define HW4  784           // HW/4
#define NEG  (-9e15f)
#define JJ   289           // J*J

// flatnonzero(ADJ) — 49 entries
__constant__ int NZ[49] = {
      0,   1,
     17,  18,  19,
     35,  36,  40,
     54,  55,  57,
     71,  72,  73,
     89,  90,
    104, 105, 108, 109,
    125, 126, 127,
    143, 144, 147, 148, 152,
    162, 169,
    180, 181,
    197, 198, 199,
    212, 215, 216,
    229, 234, 235,
    251, 252, 253,
    269, 270,
    280, 281, 288
};

// scratch (static device globals — no allocation)
__device__ float g_avg[256 * C];   // pooled features, max batch 256
__device__ float g_B[J * C];       // collapsed linear map [17, 512]

// ---------------------------------------------------------------------------
// Fused kernel. 256 threads/block. launch_bounds(256,4) => regs<=64: ptxas
// front-batches the float4 loads (high per-warp MLP). R12/R13 A-B: regs=40
// costs ~8% HBM bandwidth, regs=64 gives 82%+.
//   blockIdx.x <  J : precompute branch — row j of B.
//   blockIdx.x >= J : pool branch — 8 warps, one (n,c) row each.
// ---------------------------------------------------------------------------
__global__ __launch_bounds__(256, 4) void fused_pool_precompute_kernel(
    const float* __restrict__ x,     // [n*C*HW]
    const float* __restrict__ e,     // [49]
    const float* __restrict__ fc1,   // [J, CA]
    const float* __restrict__ w2,    // [CA, J]  (blockdiag groups [16,J,J])
    const float* __restrict__ w1,    // [CA, C]
    float* __restrict__ avg,         // [n*C]
    float* __restrict__ B,           // [J, C]
    int rows)
{
    __shared__ float adjs[JJ];
    __shared__ float arow[J];
    __shared__ float F[CA];
    __shared__ float T[CA];

    const int t = threadIdx.x;

    if (blockIdx.x < J) {
        // ================= precompute branch: row j of B =================
        const int j = blockIdx.x;

        // fill ALL 289 slots (289 > 256: must loop — this was the R7 bug)
        for (int idx = t; idx < JJ; idx += 256) adjs[idx] = NEG;
        __syncthreads();
        if (t < 49) adjs[NZ[t]] = e[t];
        __syncthreads();

        if (t == 0) {
            float m = NEG;
#pragma unroll
            for (int k = 0; k < J; k++) m = fmaxf(m, adjs[j * J + k]);
            float s = 0.f, tmp[J];
#pragma unroll
            for (int k = 0; k < J; k++) { tmp[k] = expf(adjs[j * J + k] - m); s += tmp[k]; }
            float inv = 1.0f / s;
#pragma unroll
            for (int k = 0; k < J; k++) arow[k] = tmp[k] * inv;
        }
        __syncthreads();

        // F[k] = sum_{j2} arow[j2] * fc1[j2, k]
        for (int idx = t; idx < CA; idx += 256) {
            float s = 0.f;
#pragma unroll
            for (int j2 = 0; j2 < J; j2++) s += arow[j2] * fc1[j2 * CA + idx];
            F[idx] = s;
        }
        __syncthreads();

        // T[g*17+i] = sum_o F[g*17+o] * w2[(g*17+o)*17 + i]
        for (int idx = t; idx < CA; idx += 256) {
            int g = idx / J, i = idx % J;
            float s = 0.f;
#pragma unroll
            for (int o = 0; o < J; o++) s += F[g * J + o] * w2[(g * J + o) * J + i];
            T[idx] = s;
        }
        __syncthreads();

        // B[j, c] = sum_k T[k] * w1[k, c] — thread covers c = t and t+256.
        // Two independent chains x 4 accumulators each -> high MLP.
        {
            float a0 = 0.f, a1 = 0.f, a2 = 0.f, a3 = 0.f;
            float b0 = 0.f, b1 = 0.f, b2 = 0.f, b3 = 0.f;
#pragma unroll
            for (int k = 0; k < CA / 4; k++) {
                const float* r0 = w1 + (4 * k + 0) * C;
                const float* r1 = w1 + (4 * k + 1) * C;
                const float* r2 = w1 + (4 * k + 2) * C;
                const float* r3 = w1 + (4 * k + 3) * C;
                a0 += T[4 * k + 0] * r0[t];
                a1 += T[4 * k + 1] * r1[t];
                a2 += T[4 * k + 2] * r2[t];
                a3 += T[4 * k + 3] * r3[t];
                b0 += T[4 * k + 0] * r0[t + 256];
                b1 += T[4 * k + 1] * r1[t + 256];
                b2 += T[4 * k + 2] * r2[t + 256];
                b3 += T[4 * k + 3] * r3[t + 256];
            }
            B[j * C + t]       = (a0 + a1) + (a2 + a3);
            B[j * C + t + 256] = (b0 + b1) + (b2 + b3);
        }
    } else {
        // ---------------- pool branch: 8 warps, one (n,c) row each ------
        int warp = ((blockIdx.x - J) * 256 + t) >> 5;
        int lane = t & 31;
        if (warp >= rows) return;

        const float4* p = reinterpret_cast<const float4*>(x) + (size_t)warp * HW4;

        float4 a = make_float4(0.f, 0.f, 0.f, 0.f);
#pragma unroll
        for (int i = 0; i < 24; i++) {
            float4 v = __ldcs(&p[lane + i * 32]);
            a.x += v.x; a.y += v.y; a.z += v.z; a.w += v.w;
        }
        if (lane < 16) {                   // 784 - 24*32 = 16 tail vec4s
            float4 v = __ldcs(&p[768 + lane]);
            a.x += v.x; a.y += v.y; a.z += v.z; a.w += v.w;
        }
        float s = (a.x + a.y) + (a.z + a.w);
#pragma unroll
        for (int o = 16; o; o >>= 1) s += __shfl_xor_sync(0xffffffffu, s, o);

        if (lane == 0) avg[warp] = s * (1.0f / (float)HW);
    }
}

// ---------------------------------------------------------------------------
// Kernel 2: one block (544 threads = 17 warps) per batch element.
//   warp j:  gc[j] = relu( dot(B[j,:], avg) )
//   thread c<512: out[c] = sigmoid( dot(gc, fc2[c,:]) )
// ---------------------------------------------------------------------------
__global__ __launch_bounds__(544) void final_kernel(
    const float* __restrict__ B,     // [J, C]
    const float* __restrict__ fc2,   // [C, J]
    float* __restrict__ out)         // [n, C]
{
    __shared__ float avgs[C];
    __shared__ float gcs[J];

    const int b    = blockIdx.x;
    const int t    = threadIdx.x;
    const int wid  = t >> 5;       // 0..16
    const int lane = t & 31;

    // vectorized avg load: 128 threads x float4
    if (t < C / 4) {
        float4 v = reinterpret_cast<const float4*>(g_avg + b * C)[t];
        reinterpret_cast<float4*>(avgs)[t] = v;
    }
    __syncthreads();

    // 17 warps, one gc each
    {
        const float* wr = B + (size_t)wid * C;
        float s = 0.f;
#pragma unroll
        for (int k = lane; k < C; k += 32) s += avgs[k] * wr[k];
#pragma unroll
        for (int off = 16; off; off >>= 1) s += __shfl_xor_sync(0xffffffffu, s, off);
        if (lane == 0) gcs[wid] = fmaxf(s, 0.f);
    }
    __syncthreads();

    if (t < C) {
        const float* wr = fc2 + (size_t)t * J;
        float s = 0.f;
#pragma unroll
        for (int j = 0; j < J; j++) s += gcs[j] * wr[j];
        out[b * C + t] = 1.0f / (1.0f + expf(-s));
    }
}

// ---------------------------------------------------------------------------
extern "C" void kernel_launch(void* const* d_in, const int* in_sizes, int n_in,
                              void* d_out, int out_size)
{
    const float* x    = (const float*)d_in[0];
    const float* e    = (const float*)d_in[1];
    const float* w1   = (const float*)d_in[2];
    const float* w2   = (const float*)d_in[3];
    const float* fc1w = (const float*)d_in[4];
    const float* fc2w = (const float*)d_in[5];
    float* out = (float*)d_out;

    int n    = in_sizes[0] / (C * HW);   // 64
    int rows = n * C;                    // 32768

    float *avg, *B;
    cudaGetSymbolAddress((void**)&avg, g_avg);
    cudaGetSymbolAddress((void**)&B,  g_B);

    int grid = J + (rows + 7) / 8;       // 17 precompute + 4096 pool blocks
    fused_pool_precompute_kernel<<<grid, 256>>>(x, e, fc1w, w2, w1, avg, B, rows);

    final_kernel<<<n, 544>>>(B, fc2w, out);
}